// round 4
// baseline (speedup 1.0000x reference)
#include <cuda_runtime.h>
#include <stdint.h>

// KVGather: out[n, i, k, w, c] = r_weight[n, i, k] * kv[n, r_idx[n, i, k], w, c]
// Shapes: N=16, P2=64, TOPK=8, W2=64, C_KV=128
// Inputs (metadata order): r_idx int32 (N,P2,TOPK)  [JAX w/o x64 downcasts int64->int32],
//                          r_weight f32 (N,P2,TOPK), kv f32 (N,P2,W2,C_KV).
// Output f32 (N,P2,TOPK,W2,C_KV) = 256 MB.
//
// R2 retry: prior round failed at the container-broker level ("GB300 container
// failed twice") before any compile/run — kernel unchanged from R2 submission.

static constexpr int N    = 16;
static constexpr int P2   = 64;
static constexpr int TOPK = 8;
static constexpr int W2   = 64;
static constexpr int CKV  = 128;
static constexpr int WC   = W2 * CKV;        // 8192 floats per gathered block (32 KB)
static constexpr int WC4  = WC / 4;          // 2048 float4
static constexpr int THREADS = 256;          // 8 float4 per thread

__global__ __launch_bounds__(THREADS)
void kv_gather_kernel(const int*    __restrict__ r_idx,
                      const float*  __restrict__ r_weight,
                      const float4* __restrict__ kv4,
                      float4*       __restrict__ out4) {
    const int g = blockIdx.x;                 // 0 .. N*P2*TOPK-1 (8192)
    const int n = g >> 9;                     // / (P2*TOPK = 512)

    const int src = r_idx[g] & (P2 - 1);      // valid range [0,64); mask is free insurance
    const float wt = r_weight[g];

    const float4* __restrict__ s = kv4  + (long long)(n * P2 + src) * WC4;
    float4*       __restrict__ d = out4 + (long long)g * WC4;

    #pragma unroll 8
    for (int t = threadIdx.x; t < WC4; t += THREADS) {
        float4 v = __ldg(s + t);              // kv (32 MB) stays L2-resident
        v.x *= wt; v.y *= wt; v.z *= wt; v.w *= wt;
        __stcs(d + t, v);                     // stream the 256 MB output past L2
    }
}

extern "C" void kernel_launch(void* const* d_in, const int* in_sizes, int n_in,
                              void* d_out, int out_size) {
    const int*    r_idx    = (const int*)d_in[0];
    const float*  r_weight = (const float*)d_in[1];
    const float4* kv4      = (const float4*)d_in[2];
    float4*       out4     = (float4*)d_out;

    kv_gather_kernel<<<N * P2 * TOPK, THREADS>>>(r_idx, r_weight, kv4, out4);
}